// round 13
// baseline (speedup 1.0000x reference)
#include <cuda_runtime.h>
#include <cuda_bf16.h>

// FieldAwareFM: out[b] = sum over 780 field pairs (a<b) of
//   dot(x[b, a, b-1, :], x[b, b, a, :]),  x = input reshaped (bs, 40, 39, 16).
//
// R13 = R9 (persistent double-buffered TMA pipeline, grid=152, 4-way row
// split, early refill, parity-buffered warp_sums) with DYNAMIC row
// scheduling: blocks grab rows from a global atomic ticket counter instead
// of a static stride-152 slice. Fast SMs absorb extra rows, compressing the
// finish-time spread (L2-die variance + launch skew + the 13-vs-14 tail
// worst case). One ATOMG per row (~318 cyc) hides under the ~2.4us row
// period. Counter reset by a 1-thread kernel each launch (graph-safe,
// deterministic: every row computed exactly once into its own output slot).

#define NUM_FIELDS 40
#define COLS 39
#define EMB 16
#define ROW_FLOATS (NUM_FIELDS * COLS * EMB)      // 24960
#define ROW_F4 (ROW_FLOATS / 4)                   // 6240
#define ROW_BYTES (ROW_F4 * 16)                   // 99840
#define QCOPIES 4
#define QBYTES (ROW_BYTES / QCOPIES)              // 24960
#define QF4 (ROW_F4 / QCOPIES)                    // 1560
#define NPAIRS 780
#define WORK (NPAIRS * 4)                         // 3120 float4-pair items
#define THREADS 512
#define COMP_ITERS (WORK / THREADS)               // 6
#define COMP_REM (WORK - COMP_ITERS * THREADS)    // 48

__device__ int g_row_ctr;

extern __shared__ __align__(128) float4 sbuf[];   // 2 * ROW_F4 float4

__device__ __forceinline__ void tma_issue_row(unsigned mbar_addr,
                                              float4* sdst,
                                              const float4* gsrc)
{
    asm volatile("mbarrier.arrive.expect_tx.shared.b64 _, [%0], %1;"
                 :: "r"(mbar_addr), "r"(ROW_BYTES) : "memory");
    #pragma unroll
    for (int q = 0; q < QCOPIES; ++q) {
        unsigned d = (unsigned)__cvta_generic_to_shared(sdst + q * QF4);
        asm volatile(
            "cp.async.bulk.shared::cta.global.mbarrier::complete_tx::bytes"
            " [%0], [%1], %2, [%3];"
            :: "r"(d), "l"(gsrc + q * QF4), "r"(QBYTES), "r"(mbar_addr)
            : "memory");
    }
}

__device__ __forceinline__ void mbar_wait(unsigned mbar_addr, unsigned parity)
{
    unsigned done;
    asm volatile(
        "{\n\t.reg .pred p;\n\t"
        "mbarrier.try_wait.parity.acquire.cta.shared::cta.b64 p, [%1], %2;\n\t"
        "selp.b32 %0, 1, 0, p;\n\t}"
        : "=r"(done) : "r"(mbar_addr), "r"(parity) : "memory");
    if (!done) {
        asm volatile(
            "{\n\t.reg .pred P1;\n\t"
            "W_%=:\n\t"
            "mbarrier.try_wait.parity.acquire.cta.shared::cta.b64 P1, [%0], %1, 0x989680;\n\t"
            "@P1 bra.uni D_%=;\n\t"
            "bra.uni W_%=;\n\t"
            "D_%=:\n\t}"
            :: "r"(mbar_addr), "r"(parity) : "memory");
    }
}

__global__ void ffm_reset_kernel()
{
    g_row_ctr = 0;
}

__global__ __launch_bounds__(THREADS, 1)
void ffm_persistent_kernel(const float* __restrict__ in,
                           float* __restrict__ out, int nrows)
{
    __shared__ unsigned int pair_tab[NPAIRS];     // (fA*4) | (fB*4 << 16)
    __shared__ float warp_sums[2][THREADS / 32];  // buffered on k&1
    __shared__ int srow[2];                       // row id in each buffer
    __shared__ __align__(8) unsigned long long mbar[2];

    const int tid = threadIdx.x;
    const float4* __restrict__ gin = reinterpret_cast<const float4*>(in);

    if (tid == 0) {
        #pragma unroll
        for (int c = 0; c < 2; ++c) {
            unsigned m = (unsigned)__cvta_generic_to_shared(&mbar[c]);
            asm volatile("mbarrier.init.shared.b64 [%0], %1;"
                         :: "r"(m), "r"(1) : "memory");
        }
    }

    // ---- pair table, built once per block ----
    for (int s = tid; s < NPAIRS; s += THREADS) {
        int b = (int)((1.0f + sqrtf((float)(8 * s + 1))) * 0.5f);
        if (b * (b - 1) / 2 > s)       --b;
        else if ((b + 1) * b / 2 <= s) ++b;
        const int a  = s - b * (b - 1) / 2;           // a < b
        const int fA = a * COLS + (b - 1);            // x[a][b-1]
        const int fB = b * COLS + a;                  // x[b][a]
        pair_tab[s] = (unsigned int)(fA * 4) | ((unsigned int)(fB * 4) << 16);
    }

    const unsigned m0 = (unsigned)__cvta_generic_to_shared(&mbar[0]);
    const unsigned m1 = (unsigned)__cvta_generic_to_shared(&mbar[1]);

    // ---- prologue: grab and enqueue first two rows ----
    if (tid == 0) {
        int r = atomicAdd(&g_row_ctr, 1);
        srow[0] = (r < nrows) ? r : -1;
        if (r < nrows) tma_issue_row(m0, sbuf, gin + (size_t)r * ROW_F4);
        r = atomicAdd(&g_row_ctr, 1);
        srow[1] = (r < nrows) ? r : -1;
        if (r < nrows) tma_issue_row(m1, sbuf + ROW_F4, gin + (size_t)r * ROW_F4);
    }
    __syncthreads();

    for (int k = 0; ; ++k) {
        const int cur = k & 1;
        const unsigned parity = (unsigned)((k >> 1) & 1);

        const int row = srow[cur];        // read BEFORE the post-read sync;
        if (row < 0) break;               // tid0 overwrites only after it

        mbar_wait(cur ? m1 : m0, parity);

        const float4* __restrict__ srowp = sbuf + cur * ROW_F4;
        float acc = 0.0f;
        int w = tid;
        #pragma unroll
        for (int it = 0; it < COMP_ITERS; ++it, w += THREADS) {
            const int s  = w >> 2;
            const int d4 = w & 3;
            const unsigned int pk = pair_tab[s];
            const float4 a = srowp[(int)(pk & 0xffffu) + d4];
            const float4 p = srowp[(int)(pk >> 16) + d4];
            acc = fmaf(a.x, p.x, acc);
            acc = fmaf(a.y, p.y, acc);
            acc = fmaf(a.z, p.z, acc);
            acc = fmaf(a.w, p.w, acc);
        }
        if (tid < COMP_REM) {
            const int s  = w >> 2;
            const int d4 = w & 3;
            const unsigned int pk = pair_tab[s];
            const float4 a = srowp[(int)(pk & 0xffffu) + d4];
            const float4 p = srowp[(int)(pk >> 16) + d4];
            acc = fmaf(a.x, p.x, acc);
            acc = fmaf(a.y, p.y, acc);
            acc = fmaf(a.z, p.z, acc);
            acc = fmaf(a.w, p.w, acc);
        }

        __syncthreads();   // all sbuf[cur] reads + srow[cur] reads complete

        // ---- grab next row, refill freed buffer IMMEDIATELY ----
        if (tid == 0) {
            int r = atomicAdd(&g_row_ctr, 1);
            srow[cur] = (r < nrows) ? r : -1;
            if (r < nrows)
                tma_issue_row(cur ? m1 : m0, sbuf + cur * ROW_F4,
                              gin + (size_t)r * ROW_F4);
        }

        // ---- block reduction (warp_sums slot = k&1) ----
        #pragma unroll
        for (int o = 16; o > 0; o >>= 1)
            acc += __shfl_down_sync(0xffffffffu, acc, o);
        if ((tid & 31) == 0)
            warp_sums[cur][tid >> 5] = acc;
        __syncthreads();   // also publishes tid0's srow[cur] update
        if (tid < (THREADS / 32)) {
            acc = warp_sums[cur][tid];
            #pragma unroll
            for (int o = (THREADS / 64); o > 0; o >>= 1)
                acc += __shfl_down_sync(0x0000ffffu, acc, o);
            if (tid == 0)
                out[row] = acc;
        }
        // warp_sums[cur] next written two rows later, after that row's
        // post-read __syncthreads — safe without another barrier here.
    }
}

extern "C" void kernel_launch(void* const* d_in, const int* in_sizes, int n_in,
                              void* d_out, int out_size)
{
    const float* in = (const float*)d_in[0];
    float* out = (float*)d_out;
    const int bs = in_sizes[0] / ROW_FLOATS;   // 2048

    int sms = 148;
    cudaDeviceGetAttribute(&sms, cudaDevAttrMultiProcessorCount, 0);

    cudaFuncSetAttribute(ffm_persistent_kernel,
                         cudaFuncAttributeMaxDynamicSharedMemorySize,
                         2 * ROW_BYTES);

    ffm_reset_kernel<<<1, 1>>>();
    ffm_persistent_kernel<<<sms, THREADS, 2 * ROW_BYTES>>>(in, out, bs);
}

// round 14
// speedup vs baseline: 1.0108x; 1.0108x over previous
#include <cuda_runtime.h>
#include <cuda_bf16.h>

// FieldAwareFM: out[b] = sum over 780 field pairs (a<b) of
//   dot(x[b, a, b-1, :], x[b, b, a, :]),  x = input reshaped (bs, 40, 39, 16).
//
// FINAL (== R9, the measured optimum at 35.30us / 6.16 TB/s):
// persistent, double-buffered TMA pipeline.
//  * grid = #SMs (152), one 512-thread block per SM, 2 full 99840-B row
//    buffers in smem; block walks rows blockIdx.x + k*grid (static stride --
//    dynamic scheduling regressed: the serialized ATOMG sat on the refill
//    critical path).
//  * each row fetched as FOUR 24960-B cp.async.bulk copies completing on one
//    mbarrier (4-way split measured optimal: 1-way and 8-way both slower).
//  * refill of row k+2 issued immediately after the post-read sync, before
//    the reduction.
//  * read-once pair traversal (each element loaded exactly once from DRAM;
//    gather resolved in smem) -> traffic == input size, cache-independent.
// Exhausted null levers: L2 prefetch (x3), contiguous per-SM ranges,
// grid=128, dynamic work stealing -- all neutral or negative. Bandwidth is
// pinned at ~6.1-6.2 TB/s aggregate for this mix; this config sits on it.

#define NUM_FIELDS 40
#define COLS 39
#define EMB 16
#define ROW_FLOATS (NUM_FIELDS * COLS * EMB)      // 24960
#define ROW_F4 (ROW_FLOATS / 4)                   // 6240
#define ROW_BYTES (ROW_F4 * 16)                   // 99840
#define QCOPIES 4
#define QBYTES (ROW_BYTES / QCOPIES)              // 24960
#define QF4 (ROW_F4 / QCOPIES)                    // 1560
#define NPAIRS 780
#define WORK (NPAIRS * 4)                         // 3120 float4-pair items
#define THREADS 512
#define COMP_ITERS (WORK / THREADS)               // 6
#define COMP_REM (WORK - COMP_ITERS * THREADS)    // 48

extern __shared__ __align__(128) float4 sbuf[];   // 2 * ROW_F4 float4

__device__ __forceinline__ void tma_issue_row(unsigned mbar_addr,
                                              float4* sdst,
                                              const float4* gsrc)
{
    asm volatile("mbarrier.arrive.expect_tx.shared.b64 _, [%0], %1;"
                 :: "r"(mbar_addr), "r"(ROW_BYTES) : "memory");
    #pragma unroll
    for (int q = 0; q < QCOPIES; ++q) {
        unsigned d = (unsigned)__cvta_generic_to_shared(sdst + q * QF4);
        asm volatile(
            "cp.async.bulk.shared::cta.global.mbarrier::complete_tx::bytes"
            " [%0], [%1], %2, [%3];"
            :: "r"(d), "l"(gsrc + q * QF4), "r"(QBYTES), "r"(mbar_addr)
            : "memory");
    }
}

__device__ __forceinline__ void mbar_wait(unsigned mbar_addr, unsigned parity)
{
    unsigned done;
    asm volatile(
        "{\n\t.reg .pred p;\n\t"
        "mbarrier.try_wait.parity.acquire.cta.shared::cta.b64 p, [%1], %2;\n\t"
        "selp.b32 %0, 1, 0, p;\n\t}"
        : "=r"(done) : "r"(mbar_addr), "r"(parity) : "memory");
    if (!done) {
        asm volatile(
            "{\n\t.reg .pred P1;\n\t"
            "W_%=:\n\t"
            "mbarrier.try_wait.parity.acquire.cta.shared::cta.b64 P1, [%0], %1, 0x989680;\n\t"
            "@P1 bra.uni D_%=;\n\t"
            "bra.uni W_%=;\n\t"
            "D_%=:\n\t}"
            :: "r"(mbar_addr), "r"(parity) : "memory");
    }
}

__global__ __launch_bounds__(THREADS, 1)
void ffm_persistent_kernel(const float* __restrict__ in,
                           float* __restrict__ out, int nrows)
{
    __shared__ unsigned int pair_tab[NPAIRS];     // (fA*4) | (fB*4 << 16)
    __shared__ float warp_sums[THREADS / 32];
    __shared__ __align__(8) unsigned long long mbar[2];

    const int tid  = threadIdx.x;
    const int nblk = gridDim.x;
    const int myrows = (nrows - blockIdx.x + nblk - 1) / nblk;
    const float4* __restrict__ gin = reinterpret_cast<const float4*>(in);

    if (tid == 0) {
        #pragma unroll
        for (int c = 0; c < 2; ++c) {
            unsigned m = (unsigned)__cvta_generic_to_shared(&mbar[c]);
            asm volatile("mbarrier.init.shared.b64 [%0], %1;"
                         :: "r"(m), "r"(1) : "memory");
        }
    }

    // ---- pair table, built once per block ----
    for (int s = tid; s < NPAIRS; s += THREADS) {
        int b = (int)((1.0f + sqrtf((float)(8 * s + 1))) * 0.5f);
        if (b * (b - 1) / 2 > s)       --b;
        else if ((b + 1) * b / 2 <= s) ++b;
        const int a  = s - b * (b - 1) / 2;           // a < b
        const int fA = a * COLS + (b - 1);            // x[a][b-1]
        const int fB = b * COLS + a;                  // x[b][a]
        pair_tab[s] = (unsigned int)(fA * 4) | ((unsigned int)(fB * 4) << 16);
    }
    __syncthreads();

    const unsigned m0 = (unsigned)__cvta_generic_to_shared(&mbar[0]);
    const unsigned m1 = (unsigned)__cvta_generic_to_shared(&mbar[1]);

    // ---- prologue: enqueue rows 0 and 1 ----
    if (tid == 0) {
        if (myrows > 0)
            tma_issue_row(m0, sbuf, gin + (size_t)blockIdx.x * ROW_F4);
        if (myrows > 1)
            tma_issue_row(m1, sbuf + ROW_F4,
                          gin + (size_t)(blockIdx.x + nblk) * ROW_F4);
    }

    for (int k = 0; k < myrows; ++k) {
        const int cur = k & 1;
        const unsigned parity = (unsigned)((k >> 1) & 1);
        mbar_wait(cur ? m1 : m0, parity);

        const float4* __restrict__ srow = sbuf + cur * ROW_F4;
        float acc = 0.0f;
        int w = tid;
        #pragma unroll
        for (int it = 0; it < COMP_ITERS; ++it, w += THREADS) {
            const int s  = w >> 2;
            const int d4 = w & 3;
            const unsigned int pk = pair_tab[s];
            const float4 a = srow[(int)(pk & 0xffffu) + d4];
            const float4 p = srow[(int)(pk >> 16) + d4];
            acc = fmaf(a.x, p.x, acc);
            acc = fmaf(a.y, p.y, acc);
            acc = fmaf(a.z, p.z, acc);
            acc = fmaf(a.w, p.w, acc);
        }
        if (tid < COMP_REM) {
            const int s  = w >> 2;
            const int d4 = w & 3;
            const unsigned int pk = pair_tab[s];
            const float4 a = srow[(int)(pk & 0xffffu) + d4];
            const float4 p = srow[(int)(pk >> 16) + d4];
            acc = fmaf(a.x, p.x, acc);
            acc = fmaf(a.y, p.y, acc);
            acc = fmaf(a.z, p.z, acc);
            acc = fmaf(a.w, p.w, acc);
        }

        __syncthreads();   // all sbuf[cur] reads complete

        // ---- refill freed buffer with row k+2 IMMEDIATELY ----
        if (tid == 0 && k + 2 < myrows)
            tma_issue_row(cur ? m1 : m0, sbuf + cur * ROW_F4,
                          gin + (size_t)(blockIdx.x + (size_t)(k + 2) * nblk) * ROW_F4);

        // ---- block reduction for this row ----
        #pragma unroll
        for (int o = 16; o > 0; o >>= 1)
            acc += __shfl_down_sync(0xffffffffu, acc, o);
        if ((tid & 31) == 0)
            warp_sums[tid >> 5] = acc;
        __syncthreads();
        if (tid < (THREADS / 32)) {
            acc = warp_sums[tid];
            #pragma unroll
            for (int o = (THREADS / 64); o > 0; o >>= 1)
                acc += __shfl_down_sync(0x0000ffffu, acc, o);
            if (tid == 0)
                out[blockIdx.x + (size_t)k * nblk] = acc;
        }
        __syncthreads();   // protect warp_sums for the next iteration
    }
}

extern "C" void kernel_launch(void* const* d_in, const int* in_sizes, int n_in,
                              void* d_out, int out_size)
{
    const float* in = (const float*)d_in[0];
    float* out = (float*)d_out;
    const int bs = in_sizes[0] / ROW_FLOATS;   // 2048

    int sms = 148;
    cudaDeviceGetAttribute(&sms, cudaDevAttrMultiProcessorCount, 0);

    cudaFuncSetAttribute(ffm_persistent_kernel,
                         cudaFuncAttributeMaxDynamicSharedMemorySize,
                         2 * ROW_BYTES);
    ffm_persistent_kernel<<<sms, THREADS, 2 * ROW_BYTES>>>(in, out, bs);
}

// round 15
// speedup vs baseline: 1.0181x; 1.0073x over previous
#include <cuda_runtime.h>
#include <cuda_bf16.h>

// FieldAwareFM: out[b] = sum over 780 field pairs (a<b) of
//   dot(x[b, a, b-1, :], x[b, b, a, :]),  x = input reshaped (bs, 40, 39, 16).
//
// FINAL: persistent, double-buffered TMA pipeline (the R9 measured optimum,
// 35.3us / 6.16 TB/s) with the prologue reordered so the first TMA issues
// BEFORE the pair-table build (table construction hides under the in-flight
// first-row copy; same-thread init->fence.proxy.async->issue ordering).
//
//  * grid = #SMs, one 512-thread block per SM, 2 full 99840-B row buffers.
//  * each row = FOUR 24960-B cp.async.bulk copies on one mbarrier
//    (4-way split measured optimal; 1-way and 8-way both slower).
//  * refill of row k+2 issued immediately after the post-read sync.
//  * read-once pair traversal: every element fetched exactly once from DRAM,
//    gather resolved in smem -> traffic == input size, cache-independent.
//
// Tested-null levers (do not revisit): L2 prefetch x3, contiguous per-SM
// ranges, grid=128, dynamic work stealing, 8-way split, involution traversal.

#define NUM_FIELDS 40
#define COLS 39
#define EMB 16
#define ROW_FLOATS (NUM_FIELDS * COLS * EMB)      // 24960
#define ROW_F4 (ROW_FLOATS / 4)                   // 6240
#define ROW_BYTES (ROW_F4 * 16)                   // 99840
#define QCOPIES 4
#define QBYTES (ROW_BYTES / QCOPIES)              // 24960
#define QF4 (ROW_F4 / QCOPIES)                    // 1560
#define NPAIRS 780
#define WORK (NPAIRS * 4)                         // 3120 float4-pair items
#define THREADS 512
#define COMP_ITERS (WORK / THREADS)               // 6
#define COMP_REM (WORK - COMP_ITERS * THREADS)    // 48

extern __shared__ __align__(128) float4 sbuf[];   // 2 * ROW_F4 float4

__device__ __forceinline__ void tma_issue_row(unsigned mbar_addr,
                                              float4* sdst,
                                              const float4* gsrc)
{
    asm volatile("mbarrier.arrive.expect_tx.shared.b64 _, [%0], %1;"
                 :: "r"(mbar_addr), "r"(ROW_BYTES) : "memory");
    #pragma unroll
    for (int q = 0; q < QCOPIES; ++q) {
        unsigned d = (unsigned)__cvta_generic_to_shared(sdst + q * QF4);
        asm volatile(
            "cp.async.bulk.shared::cta.global.mbarrier::complete_tx::bytes"
            " [%0], [%1], %2, [%3];"
            :: "r"(d), "l"(gsrc + q * QF4), "r"(QBYTES), "r"(mbar_addr)
            : "memory");
    }
}

__device__ __forceinline__ void mbar_wait(unsigned mbar_addr, unsigned parity)
{
    unsigned done;
    asm volatile(
        "{\n\t.reg .pred p;\n\t"
        "mbarrier.try_wait.parity.acquire.cta.shared::cta.b64 p, [%1], %2;\n\t"
        "selp.b32 %0, 1, 0, p;\n\t}"
        : "=r"(done) : "r"(mbar_addr), "r"(parity) : "memory");
    if (!done) {
        asm volatile(
            "{\n\t.reg .pred P1;\n\t"
            "W_%=:\n\t"
            "mbarrier.try_wait.parity.acquire.cta.shared::cta.b64 P1, [%0], %1, 0x989680;\n\t"
            "@P1 bra.uni D_%=;\n\t"
            "bra.uni W_%=;\n\t"
            "D_%=:\n\t}"
            :: "r"(mbar_addr), "r"(parity) : "memory");
    }
}

__global__ __launch_bounds__(THREADS, 1)
void ffm_persistent_kernel(const float* __restrict__ in,
                           float* __restrict__ out, int nrows)
{
    __shared__ unsigned int pair_tab[NPAIRS];     // (fA*4) | (fB*4 << 16)
    __shared__ float warp_sums[THREADS / 32];
    __shared__ __align__(8) unsigned long long mbar[2];

    const int tid  = threadIdx.x;
    const int nblk = gridDim.x;
    const int myrows = (nrows - blockIdx.x + nblk - 1) / nblk;
    const float4* __restrict__ gin = reinterpret_cast<const float4*>(in);

    // ---- prologue: init barriers and launch rows 0+1 FIRST (tid0 only;
    //      same-thread ordering, async proxy fenced after init) ----
    if (tid == 0) {
        #pragma unroll
        for (int c = 0; c < 2; ++c) {
            unsigned m = (unsigned)__cvta_generic_to_shared(&mbar[c]);
            asm volatile("mbarrier.init.shared.b64 [%0], %1;"
                         :: "r"(m), "r"(1) : "memory");
        }
        asm volatile("fence.proxy.async.shared::cta;" ::: "memory");
        const unsigned m0 = (unsigned)__cvta_generic_to_shared(&mbar[0]);
        const unsigned m1 = (unsigned)__cvta_generic_to_shared(&mbar[1]);
        if (myrows > 0)
            tma_issue_row(m0, sbuf, gin + (size_t)blockIdx.x * ROW_F4);
        if (myrows > 1)
            tma_issue_row(m1, sbuf + ROW_F4,
                          gin + (size_t)(blockIdx.x + nblk) * ROW_F4);
    }

    // ---- pair table built UNDER the in-flight first-row copy ----
    for (int s = tid; s < NPAIRS; s += THREADS) {
        int b = (int)((1.0f + sqrtf((float)(8 * s + 1))) * 0.5f);
        if (b * (b - 1) / 2 > s)       --b;
        else if ((b + 1) * b / 2 <= s) ++b;
        const int a  = s - b * (b - 1) / 2;           // a < b
        const int fA = a * COLS + (b - 1);            // x[a][b-1]
        const int fB = b * COLS + a;                  // x[b][a]
        pair_tab[s] = (unsigned int)(fA * 4) | ((unsigned int)(fB * 4) << 16);
    }
    __syncthreads();   // publishes mbar init + pair_tab to all threads

    const unsigned m0 = (unsigned)__cvta_generic_to_shared(&mbar[0]);
    const unsigned m1 = (unsigned)__cvta_generic_to_shared(&mbar[1]);

    for (int k = 0; k < myrows; ++k) {
        const int cur = k & 1;
        const unsigned parity = (unsigned)((k >> 1) & 1);
        mbar_wait(cur ? m1 : m0, parity);

        const float4* __restrict__ srow = sbuf + cur * ROW_F4;
        float acc = 0.0f;
        int w = tid;
        #pragma unroll
        for (int it = 0; it < COMP_ITERS; ++it, w += THREADS) {
            const int s  = w >> 2;
            const int d4 = w & 3;
            const unsigned int pk = pair_tab[s];
            const float4 a = srow[(int)(pk & 0xffffu) + d4];
            const float4 p = srow[(int)(pk >> 16) + d4];
            acc = fmaf(a.x, p.x, acc);
            acc = fmaf(a.y, p.y, acc);
            acc = fmaf(a.z, p.z, acc);
            acc = fmaf(a.w, p.w, acc);
        }
        if (tid < COMP_REM) {
            const int s  = w >> 2;
            const int d4 = w & 3;
            const unsigned int pk = pair_tab[s];
            const float4 a = srow[(int)(pk & 0xffffu) + d4];
            const float4 p = srow[(int)(pk >> 16) + d4];
            acc = fmaf(a.x, p.x, acc);
            acc = fmaf(a.y, p.y, acc);
            acc = fmaf(a.z, p.z, acc);
            acc = fmaf(a.w, p.w, acc);
        }

        __syncthreads();   // all sbuf[cur] reads complete

        // ---- refill freed buffer with row k+2 IMMEDIATELY ----
        if (tid == 0 && k + 2 < myrows)
            tma_issue_row(cur ? m1 : m0, sbuf + cur * ROW_F4,
                          gin + (size_t)(blockIdx.x + (size_t)(k + 2) * nblk) * ROW_F4);

        // ---- block reduction for this row ----
        #pragma unroll
        for (int o = 16; o > 0; o >>= 1)
            acc += __shfl_down_sync(0xffffffffu, acc, o);
        if ((tid & 31) == 0)
            warp_sums[tid >> 5] = acc;
        __syncthreads();
        if (tid < (THREADS / 32)) {
            acc = warp_sums[tid];
            #pragma unroll
            for (int o = (THREADS / 64); o > 0; o >>= 1)
                acc += __shfl_down_sync(0x0000ffffu, acc, o);
            if (tid == 0)
                out[blockIdx.x + (size_t)k * nblk] = acc;
        }
        __syncthreads();   // protect warp_sums for the next iteration
    }
}

extern "C" void kernel_launch(void* const* d_in, const int* in_sizes, int n_in,
                              void* d_out, int out_size)
{
    const float* in = (const float*)d_in[0];
    float* out = (float*)d_out;
    const int bs = in_sizes[0] / ROW_FLOATS;   // 2048

    int sms = 148;
    cudaDeviceGetAttribute(&sms, cudaDevAttrMultiProcessorCount, 0);

    cudaFuncSetAttribute(ffm_persistent_kernel,
                         cudaFuncAttributeMaxDynamicSharedMemorySize,
                         2 * ROW_BYTES);
    ffm_persistent_kernel<<<sms, THREADS, 2 * ROW_BYTES>>>(in, out, bs);
}

// round 16
// speedup vs baseline: 1.0209x; 1.0027x over previous
#include <cuda_runtime.h>
#include <cuda_bf16.h>

// FieldAwareFM: out[b] = sum over 780 field pairs (a<b) of
//   dot(x[b, a, b-1, :], x[b, b, a, :]),  x = input reshaped (bs, 40, 39, 16).
//
// FINAL: persistent, double-buffered TMA pipeline -- the twice-measured
// optimum (35.296us / ~6.1 TB/s) -- with warp_sums parity-buffered so the
// trailing per-row __syncthreads is eliminated (2 barriers/row instead of 3;
// slot cur is next written two rows later, after that row's post-read
// barrier, so ordering holds without it).
//
//  * grid = #SMs, one 512-thread block per SM, 2 full 99840-B row buffers.
//  * each row = FOUR 24960-B cp.async.bulk copies on one mbarrier
//    (4-way split measured optimal; 1-way and 8-way both slower).
//  * first TMA issued BEFORE the pair-table build (table hides under it).
//  * refill of row k+2 issued immediately after the post-read sync.
//  * read-once pair traversal: every element fetched exactly once from DRAM,
//    gather resolved in smem -> traffic == input size, cache-independent.
//
// Tested-null levers (do not revisit): L2 prefetch x3, contiguous per-SM
// ranges, grid=128, dynamic work stealing, 8-way split, involution traversal.

#define NUM_FIELDS 40
#define COLS 39
#define EMB 16
#define ROW_FLOATS (NUM_FIELDS * COLS * EMB)      // 24960
#define ROW_F4 (ROW_FLOATS / 4)                   // 6240
#define ROW_BYTES (ROW_F4 * 16)                   // 99840
#define QCOPIES 4
#define QBYTES (ROW_BYTES / QCOPIES)              // 24960
#define QF4 (ROW_F4 / QCOPIES)                    // 1560
#define NPAIRS 780
#define WORK (NPAIRS * 4)                         // 3120 float4-pair items
#define THREADS 512
#define COMP_ITERS (WORK / THREADS)               // 6
#define COMP_REM (WORK - COMP_ITERS * THREADS)    // 48

extern __shared__ __align__(128) float4 sbuf[];   // 2 * ROW_F4 float4

__device__ __forceinline__ void tma_issue_row(unsigned mbar_addr,
                                              float4* sdst,
                                              const float4* gsrc)
{
    asm volatile("mbarrier.arrive.expect_tx.shared.b64 _, [%0], %1;"
                 :: "r"(mbar_addr), "r"(ROW_BYTES) : "memory");
    #pragma unroll
    for (int q = 0; q < QCOPIES; ++q) {
        unsigned d = (unsigned)__cvta_generic_to_shared(sdst + q * QF4);
        asm volatile(
            "cp.async.bulk.shared::cta.global.mbarrier::complete_tx::bytes"
            " [%0], [%1], %2, [%3];"
            :: "r"(d), "l"(gsrc + q * QF4), "r"(QBYTES), "r"(mbar_addr)
            : "memory");
    }
}

__device__ __forceinline__ void mbar_wait(unsigned mbar_addr, unsigned parity)
{
    unsigned done;
    asm volatile(
        "{\n\t.reg .pred p;\n\t"
        "mbarrier.try_wait.parity.acquire.cta.shared::cta.b64 p, [%1], %2;\n\t"
        "selp.b32 %0, 1, 0, p;\n\t}"
        : "=r"(done) : "r"(mbar_addr), "r"(parity) : "memory");
    if (!done) {
        asm volatile(
            "{\n\t.reg .pred P1;\n\t"
            "W_%=:\n\t"
            "mbarrier.try_wait.parity.acquire.cta.shared::cta.b64 P1, [%0], %1, 0x989680;\n\t"
            "@P1 bra.uni D_%=;\n\t"
            "bra.uni W_%=;\n\t"
            "D_%=:\n\t}"
            :: "r"(mbar_addr), "r"(parity) : "memory");
    }
}

__global__ __launch_bounds__(THREADS, 1)
void ffm_persistent_kernel(const float* __restrict__ in,
                           float* __restrict__ out, int nrows)
{
    __shared__ unsigned int pair_tab[NPAIRS];     // (fA*4) | (fB*4 << 16)
    __shared__ float warp_sums[2][THREADS / 32];  // parity-buffered on k&1
    __shared__ __align__(8) unsigned long long mbar[2];

    const int tid  = threadIdx.x;
    const int nblk = gridDim.x;
    const int myrows = (nrows - blockIdx.x + nblk - 1) / nblk;
    const float4* __restrict__ gin = reinterpret_cast<const float4*>(in);

    // ---- prologue: init barriers and launch rows 0+1 FIRST (tid0 only;
    //      same-thread ordering, async proxy fenced after init) ----
    if (tid == 0) {
        #pragma unroll
        for (int c = 0; c < 2; ++c) {
            unsigned m = (unsigned)__cvta_generic_to_shared(&mbar[c]);
            asm volatile("mbarrier.init.shared.b64 [%0], %1;"
                         :: "r"(m), "r"(1) : "memory");
        }
        asm volatile("fence.proxy.async.shared::cta;" ::: "memory");
        const unsigned pm0 = (unsigned)__cvta_generic_to_shared(&mbar[0]);
        const unsigned pm1 = (unsigned)__cvta_generic_to_shared(&mbar[1]);
        if (myrows > 0)
            tma_issue_row(pm0, sbuf, gin + (size_t)blockIdx.x * ROW_F4);
        if (myrows > 1)
            tma_issue_row(pm1, sbuf + ROW_F4,
                          gin + (size_t)(blockIdx.x + nblk) * ROW_F4);
    }

    // ---- pair table built UNDER the in-flight first-row copy ----
    for (int s = tid; s < NPAIRS; s += THREADS) {
        int b = (int)((1.0f + sqrtf((float)(8 * s + 1))) * 0.5f);
        if (b * (b - 1) / 2 > s)       --b;
        else if ((b + 1) * b / 2 <= s) ++b;
        const int a  = s - b * (b - 1) / 2;           // a < b
        const int fA = a * COLS + (b - 1);            // x[a][b-1]
        const int fB = b * COLS + a;                  // x[b][a]
        pair_tab[s] = (unsigned int)(fA * 4) | ((unsigned int)(fB * 4) << 16);
    }
    __syncthreads();   // publishes mbar init + pair_tab to all threads

    const unsigned m0 = (unsigned)__cvta_generic_to_shared(&mbar[0]);
    const unsigned m1 = (unsigned)__cvta_generic_to_shared(&mbar[1]);

    for (int k = 0; k < myrows; ++k) {
        const int cur = k & 1;
        const unsigned parity = (unsigned)((k >> 1) & 1);
        mbar_wait(cur ? m1 : m0, parity);

        const float4* __restrict__ srow = sbuf + cur * ROW_F4;
        float acc = 0.0f;
        int w = tid;
        #pragma unroll
        for (int it = 0; it < COMP_ITERS; ++it, w += THREADS) {
            const int s  = w >> 2;
            const int d4 = w & 3;
            const unsigned int pk = pair_tab[s];
            const float4 a = srow[(int)(pk & 0xffffu) + d4];
            const float4 p = srow[(int)(pk >> 16) + d4];
            acc = fmaf(a.x, p.x, acc);
            acc = fmaf(a.y, p.y, acc);
            acc = fmaf(a.z, p.z, acc);
            acc = fmaf(a.w, p.w, acc);
        }
        if (tid < COMP_REM) {
            const int s  = w >> 2;
            const int d4 = w & 3;
            const unsigned int pk = pair_tab[s];
            const float4 a = srow[(int)(pk & 0xffffu) + d4];
            const float4 p = srow[(int)(pk >> 16) + d4];
            acc = fmaf(a.x, p.x, acc);
            acc = fmaf(a.y, p.y, acc);
            acc = fmaf(a.z, p.z, acc);
            acc = fmaf(a.w, p.w, acc);
        }

        __syncthreads();   // all sbuf[cur] reads complete

        // ---- refill freed buffer with row k+2 IMMEDIATELY ----
        if (tid == 0 && k + 2 < myrows)
            tma_issue_row(cur ? m1 : m0, sbuf + cur * ROW_F4,
                          gin + (size_t)(blockIdx.x + (size_t)(k + 2) * nblk) * ROW_F4);

        // ---- block reduction (warp_sums slot = k&1; no trailing sync:
        //      slot cur is next written two rows later, after that row's
        //      post-read __syncthreads) ----
        #pragma unroll
        for (int o = 16; o > 0; o >>= 1)
            acc += __shfl_down_sync(0xffffffffu, acc, o);
        if ((tid & 31) == 0)
            warp_sums[cur][tid >> 5] = acc;
        __syncthreads();
        if (tid < (THREADS / 32)) {
            acc = warp_sums[cur][tid];
            #pragma unroll
            for (int o = (THREADS / 64); o > 0; o >>= 1)
                acc += __shfl_down_sync(0x0000ffffu, acc, o);
            if (tid == 0)
                out[blockIdx.x + (size_t)k * nblk] = acc;
        }
    }
}

extern "C" void kernel_launch(void* const* d_in, const int* in_sizes, int n_in,
                              void* d_out, int out_size)
{
    const float* in = (const float*)d_in[0];
    float* out = (float*)d_out;
    const int bs = in_sizes[0] / ROW_FLOATS;   // 2048

    int sms = 148;
    cudaDeviceGetAttribute(&sms, cudaDevAttrMultiProcessorCount, 0);

    cudaFuncSetAttribute(ffm_persistent_kernel,
                         cudaFuncAttributeMaxDynamicSharedMemorySize,
                         2 * ROW_BYTES);
    ffm_persistent_kernel<<<sms, THREADS, 2 * ROW_BYTES>>>(in, out, bs);
}